// round 1
// baseline (speedup 1.0000x reference)
#include <cuda_runtime.h>
#include <math.h>
#include <stdint.h>

#define NB 128
#define NJ 32
#define NI 1152
#define NN 16
#define TI 32
#define NTILES (NI / TI)   // 36

// ---------- global scratch (no allocation allowed) ----------
__device__ float    g_V0[NB * NJ * NN];
__device__ float    g_V1[NB * NJ * NN];
__device__ float    g_S_part[NTILES * NB * NJ * NN];   // per-tile s partials
__device__ float    g_sc_part[NTILES * NB * NJ];       // per-tile score partials
__device__ float    g_ent_part[2 * NTILES * NB];       // entropy partials (slots 0,1)
__device__ unsigned g_mask1[NB];
__device__ unsigned g_mask2[NB];

// ---------- smem layout (words) for stream kernel ----------
#define TILE_OFF  0
#define TILE_JSTR 545            // 32*17 + 1 pad -> bank-safe in every phase
#define TILE_ISTR 17
#define DOTS_OFF  17440          // 32*545
#define DOTS_STR  33
#define VS0_OFF   18496          // +32*33
#define VS1_OFF   19008
#define RED_OFF   19520
#define SMEM_WORDS 19528
#define SMEM_BYTES (SMEM_WORDS * 4)

__device__ __forceinline__ float wsum32(float v) {
#pragma unroll
    for (int o = 16; o; o >>= 1) v += __shfl_xor_sync(0xFFFFFFFFu, v, o);
    return v;
}
__device__ __forceinline__ float wmax32(float v) {
#pragma unroll
    for (int o = 16; o; o >>= 1) v = fmaxf(v, __shfl_xor_sync(0xFFFFFFFFu, v, o));
    return v;
}

// =====================================================================
// Pass 1: s0 = (1/32) * sum_i u_hat[b,j,i,:] ; v0 = squash(s0 + bias)
// one block per (j, b); pure coalesced streaming reduction
// =====================================================================
__global__ void __launch_bounds__(256) pass1_kernel(const float* __restrict__ u,
                                                    const float* __restrict__ bias) {
    __shared__ float sred[64 * 17];
    int j = blockIdx.x, b = blockIdx.y;
    int t = threadIdx.x;
    int q = t & 3, ir = t >> 2;              // 64 row-groups x 4 quads
    const float* base = u + (size_t)(b * NJ + j) * (NI * NN);
    float4 acc = make_float4(0.f, 0.f, 0.f, 0.f);
#pragma unroll
    for (int k = 0; k < 18; ++k) {
        int i = ir + k * 64;
        float4 v = *reinterpret_cast<const float4*>(base + (size_t)i * NN + q * 4);
        acc.x += v.x; acc.y += v.y; acc.z += v.z; acc.w += v.w;
    }
    float* sp = sred + ir * 17 + q * 4;
    sp[0] = acc.x; sp[1] = acc.y; sp[2] = acc.z; sp[3] = acc.w;
    __syncthreads();
    if (t < 16) {
        int n = t;
        float s = 0.f;
        for (int r = 0; r < 64; ++r) s += sred[r * 17 + n];
        s *= (1.f / 32.f);
        float ss = s;
#pragma unroll
        for (int o = 8; o; o >>= 1) ss += __shfl_xor_sync(0xFFFFu, ss, o);
        float tb = (ss == 0.f) ? 0.f : (s + bias[j * NN + n]);
        float sq = tb * tb;
#pragma unroll
        for (int o = 8; o; o >>= 1) sq += __shfl_xor_sync(0xFFFFu, sq, o);
        float v = (sq / (1.f + sq)) * tb / sqrtf(sq + 1e-8f);
        g_V0[(b * NJ + j) * NN + n] = v;
    }
}

// =====================================================================
// Streaming kernel: per (b, i-tile) recompute routing logits from u·v,
// masked softmax over j, then either accumulate node scores (IS_SCORE)
// or accumulate s[b,j,n] + entropy (!IS_SCORE).
// =====================================================================
template <bool IS_SCORE, bool USE_V1>
__global__ void __launch_bounds__(256, 2) stream_kernel(const float* __restrict__ u,
                                                        int mask_sel, int ent_slot) {
    extern __shared__ float sm[];
    float* tile  = sm + TILE_OFF;
    float* sdots = sm + DOTS_OFF;
    float* svs0  = sm + VS0_OFF;
    float* svs1  = sm + VS1_OFF;
    float* red   = sm + RED_OFF;

    int t = threadIdx.x, lane = t & 31, w = t >> 5;
    int tb = blockIdx.x, b = blockIdx.y;
    int i0 = tb * TI;
    const float* gb = u + (size_t)b * (NJ * NI * NN) + (size_t)i0 * NN;

    // stage v vectors
    svs0[t]       = g_V0[b * (NJ * NN) + t];
    svs0[t + 256] = g_V0[b * (NJ * NN) + 256 + t];
    if (USE_V1) {
        svs1[t]       = g_V1[b * (NJ * NN) + t];
        svs1[t + 256] = g_V1[b * (NJ * NN) + 256 + t];
    }

    // load tile: 32 j x 32 i x 16 n  (float4 global, scalar swizzled smem)
    float4 r[16];
#pragma unroll
    for (int k = 0; k < 16; ++k) {
        int idx = k * 256 + t;
        int j = idx >> 7, rr = idx & 127;
        r[k] = *reinterpret_cast<const float4*>(gb + (size_t)j * (NI * NN) + rr * 4);
    }
#pragma unroll
    for (int k = 0; k < 16; ++k) {
        int idx = k * 256 + t;
        int j = idx >> 7, rr = idx & 127;
        int il = rr >> 2, q = rr & 3;
        float* tp = tile + j * TILE_JSTR + il * TILE_ISTR + q * 4;
        tp[0] = r[k].x; tp[1] = r[k].y; tp[2] = r[k].z; tp[3] = r[k].w;
    }
    __syncthreads();

    // dots: logit[il][j] = u·v0 (+ u·v1) ; warp w covers j in {w, w+8, w+16, w+24}, il = lane
#pragma unroll
    for (int p = 0; p < 4; ++p) {
        int j = w + p * 8;
        const float* tj  = tile + j * TILE_JSTR + lane * TILE_ISTR;
        const float* v0r = svs0 + j * NN;
        const float* v1r = svs1 + j * NN;
        float d = 0.f;
#pragma unroll
        for (int n = 0; n < NN; ++n) {
            float uu = tj[n];
            d += uu * v0r[n];
            if (USE_V1) d += uu * v1r[n];
        }
        sdots[lane * DOTS_STR + j] = d;
    }
    unsigned msk = (mask_sel == 0) ? 0xFFFFFFFFu
                 : (mask_sel == 1) ? g_mask1[b] : g_mask2[b];
    __syncthreads();

    // masked softmax over j (warp w owns il rows w*4 .. w*4+3), in-place c
    float ent_acc = 0.f;
#pragma unroll
    for (int s = 0; s < 4; ++s) {
        int il = w * 4 + s;
        float d   = sdots[il * DOTS_STR + lane];
        bool sel  = (msk >> lane) & 1u;
        float mx  = wmax32(sel ? d : -INFINITY);
        float e   = sel ? expf(d - mx) : 0.f;
        float S   = wsum32(e);
        float c   = e / S;
        sdots[il * DOTS_STR + lane] = c;
        if (!IS_SCORE) {
            float cd = sel ? c * d : 0.f;
            float cds = wsum32(cd);
            ent_acc += (mx + logf(S) - cds);   // -sum c*log(c)
        }
    }
    __syncthreads();

    if (IS_SCORE) {
#pragma unroll
        for (int p = 0; p < 4; ++p) {
            int j = w + p * 8;
            float c = wsum32(sdots[lane * DOTS_STR + j]);
            if (lane == 0) g_sc_part[tb * (NB * NJ) + b * NJ + j] = c;
        }
    } else {
        // s accumulation: thread owns (j=lane, n in {2w, 2w+1})
        int j = lane, n0 = w * 2;
        float a0 = 0.f, a1 = 0.f;
#pragma unroll 4
        for (int il = 0; il < TI; ++il) {
            float c = sdots[il * DOTS_STR + j];
            const float* tp = tile + j * TILE_JSTR + il * TILE_ISTR + n0;
            a0 += c * tp[0];
            a1 += c * tp[1];
        }
        size_t so = (size_t)tb * (NB * NJ * NN) + (size_t)(b * NJ + j) * NN + n0;
        g_S_part[so]     = a0;
        g_S_part[so + 1] = a1;
        if (lane == 0) red[w] = ent_acc;
        __syncthreads();
        if (t == 0) {
            float e = 0.f;
#pragma unroll
            for (int x = 0; x < 8; ++x) e += red[x];
            g_ent_part[ent_slot * (NTILES * NB) + tb * NB + b] = e;
        }
    }
}

// =====================================================================
// top-k selection per example (tie-break: lower index wins, like lax.top_k)
// =====================================================================
__global__ void topk_kernel(int K, int which) {
    int b = blockIdx.x, j = threadIdx.x;
    float sc = 0.f;
#pragma unroll 6
    for (int tt = 0; tt < NTILES; ++tt) sc += g_sc_part[tt * (NB * NJ) + b * NJ + j];
    int rank = 0;
#pragma unroll
    for (int k = 0; k < 32; ++k) {
        float o = __shfl_sync(0xFFFFFFFFu, sc, k);
        rank += (o > sc) || (o == sc && k < j);
    }
    unsigned m = __ballot_sync(0xFFFFFFFFu, rank < K);
    if (j == 0) {
        if (which == 1) g_mask1[b] = m; else g_mask2[b] = m;
    }
}

// =====================================================================
// squash from s partials (deterministic tile-order reduction)
// =====================================================================
__device__ __forceinline__ float squash_elem(int gid, const float* __restrict__ bias) {
    float s = 0.f;
#pragma unroll 6
    for (int tt = 0; tt < NTILES; ++tt) s += g_S_part[(size_t)tt * (NB * NJ * NN) + gid];
    float ss = s;
#pragma unroll
    for (int o = 8; o; o >>= 1) ss += __shfl_xor_sync(0xFFFFFFFFu, ss, o);
    int n = gid & 15, j = (gid >> 4) & 31;
    float tb = (ss == 0.f) ? 0.f : (s + bias[j * NN + n]);
    float sq = tb * tb;
#pragma unroll
    for (int o = 8; o; o >>= 1) sq += __shfl_xor_sync(0xFFFFFFFFu, sq, o);
    return (sq / (1.f + sq)) * tb / sqrtf(sq + 1e-8f);
}

__global__ void __launch_bounds__(256) squash_mid_kernel(const float* __restrict__ bias) {
    int gid = blockIdx.x * 256 + threadIdx.x;      // 65536 elems
    g_V1[gid] = squash_elem(gid, bias);
}

__global__ void __launch_bounds__(256) final_kernel(const float* __restrict__ bias,
                                                    float* __restrict__ out, int out_size) {
    int gid = blockIdx.x * 256 + threadIdx.x;
    out[gid] = squash_elem(gid, bias);
    if (blockIdx.x == 0 && threadIdx.x < NB && out_size >= NB * NJ * NN + NB * 3) {
        int b = threadIdx.x;
        float e1 = 0.f, e2 = 0.f;
        for (int tt = 0; tt < NTILES; ++tt) {
            e1 += g_ent_part[0 * (NTILES * NB) + tt * NB + b];
            e2 += g_ent_part[1 * (NTILES * NB) + tt * NB + b];
        }
        float* eo = out + NB * NJ * NN;
        eo[b * 3 + 0] = logf(32.0f);             // entropy of uniform softmax
        eo[b * 3 + 1] = e1 * (1.f / (float)NI);
        eo[b * 3 + 2] = e2 * (1.f / (float)NI);
    }
}

// =====================================================================
extern "C" void kernel_launch(void* const* d_in, const int* in_sizes, int n_in,
                              void* d_out, int out_size) {
    const float* u    = (const float*)d_in[0];
    const float* bias = (const float*)d_in[1];
    float* out        = (float*)d_out;

    cudaFuncSetAttribute(stream_kernel<true,  false>, cudaFuncAttributeMaxDynamicSharedMemorySize, SMEM_BYTES);
    cudaFuncSetAttribute(stream_kernel<false, false>, cudaFuncAttributeMaxDynamicSharedMemorySize, SMEM_BYTES);
    cudaFuncSetAttribute(stream_kernel<true,  true >, cudaFuncAttributeMaxDynamicSharedMemorySize, SMEM_BYTES);
    cudaFuncSetAttribute(stream_kernel<false, true >, cudaFuncAttributeMaxDynamicSharedMemorySize, SMEM_BYTES);

    dim3 sgrid(NTILES, NB);

    // iter 0: s0 -> v0
    pass1_kernel<<<dim3(NJ, NB), 256>>>(u, bias);
    // sparsify it=0: scores of softmax(b1), top-20
    stream_kernel<true, false><<<sgrid, 256, SMEM_BYTES>>>(u, 0, 0);
    topk_kernel<<<NB, 32>>>(20, 1);
    // iter 1: c1 (mask1), entropy1, s1 -> v1
    stream_kernel<false, false><<<sgrid, 256, SMEM_BYTES>>>(u, 1, 0);
    squash_mid_kernel<<<256, 256>>>(bias);
    // sparsify it=1: scores of softmax(b2, mask1), top-12
    stream_kernel<true, true><<<sgrid, 256, SMEM_BYTES>>>(u, 1, 0);
    topk_kernel<<<NB, 32>>>(12, 2);
    // iter 2: c2 (mask2), entropy2, s2 -> v2 (output)
    stream_kernel<false, true><<<sgrid, 256, SMEM_BYTES>>>(u, 2, 1);
    final_kernel<<<256, 256>>>(bias, out, out_size);
}

// round 2
// speedup vs baseline: 1.2843x; 1.2843x over previous
#include <cuda_runtime.h>
#include <math.h>
#include <stdint.h>

#define NB 128
#define NJ 32
#define NI 1152
#define NN 16
#define TI 32
#define NTILES (NI / TI)   // 36

// ---------- global scratch (no allocation allowed) ----------
__device__ float    g_V0[NB * NJ * NN];
__device__ float    g_V1[NB * NJ * NN];
__device__ float    g_L1[NB * NI * NJ];                // logits iter1 (b,i,j)
__device__ float    g_L2[NB * NI * NJ];                // logits iter2 (b,i,j)
__device__ float    g_S_part[NTILES * NB * NJ * NN];   // per-tile s partials
__device__ float    g_sc_part[NTILES * NB * NJ];       // per-tile score partials
__device__ float    g_ent_part[2 * NTILES * NB];       // entropy partials
__device__ unsigned g_mask1[NB];
__device__ unsigned g_mask2[NB];

#define DSTR 33

__device__ __forceinline__ float wsum32(float v) {
#pragma unroll
    for (int o = 16; o; o >>= 1) v += __shfl_xor_sync(0xFFFFFFFFu, v, o);
    return v;
}
__device__ __forceinline__ float wmax32(float v) {
#pragma unroll
    for (int o = 16; o; o >>= 1) v = fmaxf(v, __shfl_xor_sync(0xFFFFFFFFu, v, o));
    return v;
}

// =====================================================================
// Pass 1: s0 = (1/32) * sum_i u_hat[b,j,i,:] ; v0 = squash(s0 + bias)
// =====================================================================
__global__ void __launch_bounds__(256) pass1_kernel(const float* __restrict__ u,
                                                    const float* __restrict__ bias) {
    __shared__ float sred[64 * 17];
    int j = blockIdx.x, b = blockIdx.y;
    int t = threadIdx.x;
    int q = t & 3, ir = t >> 2;
    const float* base = u + (size_t)(b * NJ + j) * (NI * NN);
    float4 acc = make_float4(0.f, 0.f, 0.f, 0.f);
#pragma unroll
    for (int k = 0; k < 18; ++k) {
        int i = ir + k * 64;
        float4 v = *reinterpret_cast<const float4*>(base + (size_t)i * NN + q * 4);
        acc.x += v.x; acc.y += v.y; acc.z += v.z; acc.w += v.w;
    }
    float* sp = sred + ir * 17 + q * 4;
    sp[0] = acc.x; sp[1] = acc.y; sp[2] = acc.z; sp[3] = acc.w;
    __syncthreads();
    if (t < 16) {
        int n = t;
        float s = 0.f;
        for (int r = 0; r < 64; ++r) s += sred[r * 17 + n];
        s *= (1.f / 32.f);
        float ss = s;
#pragma unroll
        for (int o = 8; o; o >>= 1) ss += __shfl_xor_sync(0xFFFFu, ss, o);
        float tb = (ss == 0.f) ? 0.f : (s + bias[j * NN + n]);
        float sq = tb * tb;
#pragma unroll
        for (int o = 8; o; o >>= 1) sq += __shfl_xor_sync(0xFFFFu, sq, o);
        float v = (sq / (1.f + sq)) * tb / sqrtf(sq + 1e-8f);
        g_V0[(b * NJ + j) * NN + n] = v;
    }
}

// =====================================================================
// dots pass: stream u once, d = u·v (register dot, 4-lane shuffle),
// logits_out = (ADD_PREV ? logits_in + d : d); masked softmax -> node
// score partials. smem = 32x33 dots only.
// =====================================================================
template <bool ADD_PREV>
__global__ void __launch_bounds__(256) dots_kernel(const float* __restrict__ u,
                                                   const float* __restrict__ vglob,
                                                   const float* __restrict__ lin,
                                                   float* __restrict__ lout,
                                                   int mask_sel) {
    __shared__ float sd[32 * DSTR];
    int t = threadIdx.x, lane = t & 31, w = t >> 5;
    int tb = blockIdx.x, b = blockIdx.y, i0 = tb * TI;
    int q = lane & 3, ig = lane >> 2;
    const float* ub = u + (size_t)b * (NJ * NI * NN);

    // phase 1: register dots
#pragma unroll
    for (int p = 0; p < 4; ++p) {
        int j = w * 4 + p;
        float4 vj = *reinterpret_cast<const float4*>(vglob + (b * NJ + j) * NN + q * 4);
#pragma unroll
        for (int m = 0; m < 4; ++m) {
            int il = m * 8 + ig;
            float4 r = *reinterpret_cast<const float4*>(
                ub + (size_t)j * (NI * NN) + (size_t)(i0 + il) * NN + q * 4);
            float d = r.x * vj.x + r.y * vj.y + r.z * vj.z + r.w * vj.w;
            d += __shfl_xor_sync(0xFFFFFFFFu, d, 1);
            d += __shfl_xor_sync(0xFFFFFFFFu, d, 2);
            if (q == 0) sd[il * DSTR + j] = d;
        }
    }
    __syncthreads();

    // phase 2: add prev logits (if any), write logits out (coalesced)
    {
        int il = t >> 3, jq = (t & 7) * 4;
        float x0 = sd[il * DSTR + jq + 0];
        float x1 = sd[il * DSTR + jq + 1];
        float x2 = sd[il * DSTR + jq + 2];
        float x3 = sd[il * DSTR + jq + 3];
        size_t off = ((size_t)(b * NI) + i0 + il) * NJ + jq;
        if (ADD_PREV) {
            float4 pv = *reinterpret_cast<const float4*>(lin + off);
            x0 += pv.x; x1 += pv.y; x2 += pv.z; x3 += pv.w;
            sd[il * DSTR + jq + 0] = x0;
            sd[il * DSTR + jq + 1] = x1;
            sd[il * DSTR + jq + 2] = x2;
            sd[il * DSTR + jq + 3] = x3;
        }
        float4 ov = make_float4(x0, x1, x2, x3);
        *reinterpret_cast<float4*>(lout + off) = ov;
    }
    unsigned msk = (mask_sel == 0) ? 0xFFFFFFFFu : g_mask1[b];
    __syncthreads();

    // phase 3: masked softmax per i-row, write c back
#pragma unroll
    for (int s = 0; s < 4; ++s) {
        int il = w * 4 + s;
        float d = sd[il * DSTR + lane];
        bool sel = (msk >> lane) & 1u;
        float mx = wmax32(sel ? d : -INFINITY);
        float e = sel ? expf(d - mx) : 0.f;
        float S = wsum32(e);
        sd[il * DSTR + lane] = e / S;
    }
    __syncthreads();

    // phase 4: node-score partials (sum c over i-rows per j)
#pragma unroll
    for (int p = 0; p < 4; ++p) {
        int j = w * 4 + p;
        float c = wsum32(sd[lane * DSTR + j]);
        if (lane == 0) g_sc_part[tb * (NB * NJ) + b * NJ + j] = c;
    }
}

// =====================================================================
// c·s pass: read cached logits, masked softmax + entropy, then stream u
// once (coalesced) for s accumulation with shuffle-tree reduction.
// =====================================================================
__global__ void __launch_bounds__(256) csum_kernel(const float* __restrict__ u,
                                                   const float* __restrict__ lin,
                                                   int mask_sel, int ent_slot) {
    __shared__ float sd[32 * DSTR];
    __shared__ float red[8];
    int t = threadIdx.x, lane = t & 31, w = t >> 5;
    int tb = blockIdx.x, b = blockIdx.y, i0 = tb * TI;
    int q = lane & 3, ig = lane >> 2;

    // load logits tile (coalesced)
    {
        int il = t >> 3, jq = (t & 7) * 4;
        size_t off = ((size_t)(b * NI) + i0 + il) * NJ + jq;
        float4 pv = *reinterpret_cast<const float4*>(lin + off);
        sd[il * DSTR + jq + 0] = pv.x;
        sd[il * DSTR + jq + 1] = pv.y;
        sd[il * DSTR + jq + 2] = pv.z;
        sd[il * DSTR + jq + 3] = pv.w;
    }
    unsigned msk = (mask_sel == 1) ? g_mask1[b] : g_mask2[b];
    __syncthreads();

    // masked softmax + entropy per i-row
    float ent_acc = 0.f;
#pragma unroll
    for (int s = 0; s < 4; ++s) {
        int il = w * 4 + s;
        float d = sd[il * DSTR + lane];
        bool sel = (msk >> lane) & 1u;
        float mx = wmax32(sel ? d : -INFINITY);
        float e = sel ? expf(d - mx) : 0.f;
        float S = wsum32(e);
        float c = e / S;
        float cd = sel ? c * d : 0.f;
        float cds = wsum32(cd);
        ent_acc += (mx + logf(S) - cds);
        sd[il * DSTR + lane] = c;
    }
    __syncthreads();

    // s accumulation: one coalesced u sweep
    const float* ub = u + (size_t)b * (NJ * NI * NN);
#pragma unroll
    for (int p = 0; p < 4; ++p) {
        int j = w * 4 + p;
        float ax = 0.f, ay = 0.f, az = 0.f, aw = 0.f;
#pragma unroll
        for (int m = 0; m < 4; ++m) {
            int il = m * 8 + ig;
            float4 r = *reinterpret_cast<const float4*>(
                ub + (size_t)j * (NI * NN) + (size_t)(i0 + il) * NN + q * 4);
            float c = sd[il * DSTR + j];
            ax += c * r.x; ay += c * r.y; az += c * r.z; aw += c * r.w;
        }
        // reduce over the 8 ig groups (same q)
#pragma unroll
        for (int o = 4; o < 32; o <<= 1) {
            ax += __shfl_xor_sync(0xFFFFFFFFu, ax, o);
            ay += __shfl_xor_sync(0xFFFFFFFFu, ay, o);
            az += __shfl_xor_sync(0xFFFFFFFFu, az, o);
            aw += __shfl_xor_sync(0xFFFFFFFFu, aw, o);
        }
        if (ig == 0) {
            size_t so = (size_t)tb * (NB * NJ * NN) + (size_t)(b * NJ + j) * NN + q * 4;
            float4 ov = make_float4(ax, ay, az, aw);
            *reinterpret_cast<float4*>(g_S_part + so) = ov;
        }
    }

    // entropy partial
    if (lane == 0) red[w] = ent_acc;
    __syncthreads();
    if (t == 0) {
        float e = 0.f;
#pragma unroll
        for (int x = 0; x < 8; ++x) e += red[x];
        g_ent_part[ent_slot * (NTILES * NB) + tb * NB + b] = e;
    }
}

// =====================================================================
// top-k selection per example (tie-break: lower index wins)
// =====================================================================
__global__ void topk_kernel(int K, int which) {
    int b = blockIdx.x, j = threadIdx.x;
    float sc = 0.f;
#pragma unroll 6
    for (int tt = 0; tt < NTILES; ++tt) sc += g_sc_part[tt * (NB * NJ) + b * NJ + j];
    int rank = 0;
#pragma unroll
    for (int k = 0; k < 32; ++k) {
        float o = __shfl_sync(0xFFFFFFFFu, sc, k);
        rank += (o > sc) || (o == sc && k < j);
    }
    unsigned m = __ballot_sync(0xFFFFFFFFu, rank < K);
    if (j == 0) {
        if (which == 1) g_mask1[b] = m; else g_mask2[b] = m;
    }
}

// =====================================================================
// squash from s partials (deterministic tile-order reduction)
// =====================================================================
__device__ __forceinline__ float squash_elem(int gid, const float* __restrict__ bias) {
    float s = 0.f;
#pragma unroll 6
    for (int tt = 0; tt < NTILES; ++tt) s += g_S_part[(size_t)tt * (NB * NJ * NN) + gid];
    float ss = s;
#pragma unroll
    for (int o = 8; o; o >>= 1) ss += __shfl_xor_sync(0xFFFFFFFFu, ss, o);
    int n = gid & 15, j = (gid >> 4) & 31;
    float tb = (ss == 0.f) ? 0.f : (s + bias[j * NN + n]);
    float sq = tb * tb;
#pragma unroll
    for (int o = 8; o; o >>= 1) sq += __shfl_xor_sync(0xFFFFFFFFu, sq, o);
    return (sq / (1.f + sq)) * tb / sqrtf(sq + 1e-8f);
}

__global__ void __launch_bounds__(256) squash_mid_kernel(const float* __restrict__ bias) {
    int gid = blockIdx.x * 256 + threadIdx.x;
    g_V1[gid] = squash_elem(gid, bias);
}

__global__ void __launch_bounds__(256) final_kernel(const float* __restrict__ bias,
                                                    float* __restrict__ out, int out_size) {
    int gid = blockIdx.x * 256 + threadIdx.x;
    out[gid] = squash_elem(gid, bias);
    if (blockIdx.x == 0 && threadIdx.x < NB && out_size >= NB * NJ * NN + NB * 3) {
        int b = threadIdx.x;
        float e1 = 0.f, e2 = 0.f;
        for (int tt = 0; tt < NTILES; ++tt) {
            e1 += g_ent_part[0 * (NTILES * NB) + tt * NB + b];
            e2 += g_ent_part[1 * (NTILES * NB) + tt * NB + b];
        }
        float* eo = out + NB * NJ * NN;
        eo[b * 3 + 0] = logf(32.0f);
        eo[b * 3 + 1] = e1 * (1.f / (float)NI);
        eo[b * 3 + 2] = e2 * (1.f / (float)NI);
    }
}

// =====================================================================
extern "C" void kernel_launch(void* const* d_in, const int* in_sizes, int n_in,
                              void* d_out, int out_size) {
    const float* u    = (const float*)d_in[0];
    const float* bias = (const float*)d_in[1];
    float* out        = (float*)d_out;

    float *v0p, *v1p, *l1p, *l2p;
    cudaGetSymbolAddress((void**)&v0p, g_V0);
    cudaGetSymbolAddress((void**)&v1p, g_V1);
    cudaGetSymbolAddress((void**)&l1p, g_L1);
    cudaGetSymbolAddress((void**)&l2p, g_L2);

    dim3 sgrid(NTILES, NB);

    // iter 0: s0 -> v0   (u sweep #1)
    pass1_kernel<<<dim3(NJ, NB), 256>>>(u, bias);
    // logits1 = u·v0; scores of softmax(logits1); top-20  (u sweep #2)
    dots_kernel<false><<<sgrid, 256>>>(u, v0p, nullptr, l1p, 0);
    topk_kernel<<<NB, 32>>>(20, 1);
    // iter 1: c1 = softmax(logits1, mask1), entropy1, s1 -> v1  (u sweep #3)
    csum_kernel<<<sgrid, 256>>>(u, l1p, 1, 0);
    squash_mid_kernel<<<256, 256>>>(bias);
    // logits2 = logits1 + u·v1; scores of softmax(logits2, mask1); top-12 (u sweep #4)
    dots_kernel<true><<<sgrid, 256>>>(u, v1p, l1p, l2p, 1);
    topk_kernel<<<NB, 32>>>(12, 2);
    // iter 2: c2 = softmax(logits2, mask2), entropy2, s2 -> v2  (u sweep #5)
    csum_kernel<<<sgrid, 256>>>(u, l2p, 2, 1);
    final_kernel<<<256, 256>>>(bias, out, out_size);
}